// round 8
// baseline (speedup 1.0000x reference)
#include <cuda_runtime.h>

// FFM layer: out[b] = sigmoid( linear(b) + 0.5*sum_k((sum_g f)^2 - sum_g f^2) )
// f[b,g,k] = sum_d dense_x[b,d]*v[d,g,k] + sum_i v[idx[b,i],g,k]
//
// Inputs (metadata order):
//  d_in[0] dense_x  f32 [B,13]
//  d_in[1] sparse_x i32 [B,26]
//  d_in[2] W        f32 [26013]
//  d_in[3] b        f32 [1]
//  d_in[4] v        f32 [26013,39,8]
// Output: f32 [B]

namespace {
constexpr int N_DENSE  = 13;
constexpr int N_SPARSE = 26;
constexpr int ONEHOT   = 1000;
constexpr int KDIM     = 8;
constexpr int FIELDS   = N_DENSE + N_SPARSE;   // 39
constexpr int ROW      = FIELDS * KDIM;        // 312 floats per v row
constexpr int SPB      = 32;                   // samples per block
constexpr int THREADS  = SPB * KDIM;           // 256
}

__global__ __launch_bounds__(THREADS) void ffm_kernel(
    const float* __restrict__ dense_x,
    const int*   __restrict__ sparse_x,
    const float* __restrict__ W,
    const float* __restrict__ bias,
    const float* __restrict__ v,
    float*       __restrict__ out,
    int B)
{
    __shared__ float s_vd[N_DENSE * ROW];        // 4056 floats = 16224 B
    __shared__ float s_dx[SPB][N_DENSE];
    __shared__ int   s_idx[SPB][N_SPARSE];

    const int tid = threadIdx.x;
    const int b0  = blockIdx.x * SPB;

    // Stage dense slice of v (shared by every sample) into smem, vectorized.
    {
        const float4* v4  = reinterpret_cast<const float4*>(v);
        float4*       sv4 = reinterpret_cast<float4*>(s_vd);
        #pragma unroll
        for (int i = tid; i < (N_DENSE * ROW) / 4; i += THREADS)
            sv4[i] = v4[i];
    }
    // Stage dense_x for this block's 32 samples.
    for (int i = tid; i < SPB * N_DENSE; i += THREADS) {
        int s = i / N_DENSE, d = i % N_DENSE;
        int b = b0 + s;
        s_dx[s][d] = (b < B) ? dense_x[b * N_DENSE + d] : 0.0f;
    }
    // Stage global one-hot row indices.
    for (int i = tid; i < SPB * N_SPARSE; i += THREADS) {
        int s = i / N_SPARSE, f = i % N_SPARSE;
        int b = b0 + s;
        s_idx[s][f] = (b < B) ? (N_DENSE + f * ONEHOT + sparse_x[b * N_SPARSE + f])
                              : N_DENSE;   // harmless in-range dummy
    }
    __syncthreads();

    const int s = tid >> 3;   // sample within block
    const int k = tid & 7;    // latent lane owned by this thread
    const int b = b0 + s;

    float f[FIELDS];
    #pragma unroll
    for (int g = 0; g < FIELDS; ++g) f[g] = 0.0f;

    // Dense contribution: f[g] += sum_d x_d * v[d,g,k]  (smem, conflict-free)
    #pragma unroll
    for (int d = 0; d < N_DENSE; ++d) {
        const float xd = s_dx[s][d];
        const float* vd = &s_vd[d * ROW + k];
        #pragma unroll
        for (int g = 0; g < FIELDS; ++g)
            f[g] = fmaf(xd, vd[g * KDIM], f[g]);
    }

    // Sparse gathers: 26 random rows; 8-thread group reads one 32B sector per
    // (row,g); inner loop fully unrolled for MLP, outer loop rolled to keep
    // code size sane.
    #pragma unroll 1
    for (int i = 0; i < N_SPARSE; ++i) {
        const float* row = v + (size_t)s_idx[s][i] * ROW + k;
        #pragma unroll
        for (int g = 0; g < FIELDS; ++g)
            f[g] += __ldg(row + g * KDIM);
    }

    // Per-k interaction partial: 0.5 * ((sum_g f)^2 - sum_g f^2)
    float ssum = 0.0f, sqsum = 0.0f;
    #pragma unroll
    for (int g = 0; g < FIELDS; ++g) {
        ssum += f[g];
        sqsum = fmaf(f[g], f[g], sqsum);
    }
    float part = 0.5f * (ssum * ssum - sqsum);

    // Linear partials distributed over the 8 lanes of this sample.
    for (int i = k; i < N_SPARSE; i += KDIM)
        part += __ldg(W + s_idx[s][i]);
    for (int d = k; d < N_DENSE; d += KDIM)
        part += s_dx[s][d] * __ldg(W + d);

    // Reduce across the 8-lane subgroup.
    part += __shfl_down_sync(0xffffffffu, part, 4, 8);
    part += __shfl_down_sync(0xffffffffu, part, 2, 8);
    part += __shfl_down_sync(0xffffffffu, part, 1, 8);

    if (k == 0 && b < B) {
        float z = part + __ldg(bias);
        out[b] = 1.0f / (1.0f + expf(-z));
    }
}

extern "C" void kernel_launch(void* const* d_in, const int* in_sizes, int n_in,
                              void* d_out, int out_size)
{
    const float* dense_x  = (const float*)d_in[0];
    const int*   sparse_x = (const int*)  d_in[1];
    const float* W        = (const float*)d_in[2];
    const float* bias     = (const float*)d_in[3];
    const float* v        = (const float*)d_in[4];
    float*       out      = (float*)d_out;

    const int B = in_sizes[0] / N_DENSE;
    const int grid = (B + SPB - 1) / SPB;
    ffm_kernel<<<grid, THREADS>>>(dense_x, sparse_x, W, bias, v, out, B);
}

// round 9
// speedup vs baseline: 1.8369x; 1.8369x over previous
#include <cuda_runtime.h>

// FFM layer: out[b] = sigmoid( linear(b) + 0.5*sum_k((sum_g f)^2 - sum_g f^2) )
// f[b,g,k] = sum_d dense_x[b,d]*v[d,g,k] + sum_i v[idx[b,i],g,k]
//
// Inputs (metadata order):
//  d_in[0] dense_x  f32 [B,13]
//  d_in[1] sparse_x i32 [B,26]
//  d_in[2] W        f32 [26013]
//  d_in[3] b        f32 [1]
//  d_in[4] v        f32 [26013,39,8]
// Output: f32 [B]
//
// R9 design: ONE WARP PER SAMPLE. Row = 312 floats = 78 float4. Lane t owns
// float4 positions {t, t+32, t+64(t<14)} of every gathered row, so each
// LDG.128 warp instruction reads 4 fully-utilized 128B lines of one row
// (4x fewer L1 wavefronts than the 8-lanes-per-sample layout). Position
// 4t+128j has fixed k-half (t&1)*4, so the per-k reduction is a parity-
// preserving shfl tree.

namespace {
constexpr int N_DENSE  = 13;
constexpr int N_SPARSE = 26;
constexpr int ONEHOT   = 1000;
constexpr int FIELDS   = 39;
constexpr int ROW4     = FIELDS * 8 / 4;       // 78 float4 per v row
constexpr int SPB      = 8;                    // samples (warps) per block
constexpr int THREADS  = SPB * 32;             // 256
}

__device__ __forceinline__ void fma4(float4& a, float x, const float4& b) {
    a.x = fmaf(x, b.x, a.x); a.y = fmaf(x, b.y, a.y);
    a.z = fmaf(x, b.z, a.z); a.w = fmaf(x, b.w, a.w);
}
__device__ __forceinline__ void add4(float4& a, const float4& b) {
    a.x += b.x; a.y += b.y; a.z += b.z; a.w += b.w;
}
__device__ __forceinline__ void sqacc4(float4& a, const float4& b) {
    a.x = fmaf(b.x, b.x, a.x); a.y = fmaf(b.y, b.y, a.y);
    a.z = fmaf(b.z, b.z, a.z); a.w = fmaf(b.w, b.w, a.w);
}

__global__ __launch_bounds__(THREADS) void ffm_kernel(
    const float* __restrict__ dense_x,
    const int*   __restrict__ sparse_x,
    const float* __restrict__ W,
    const float* __restrict__ bias,
    const float* __restrict__ v,
    float*       __restrict__ out,
    int B)
{
    __shared__ float4 s_vd[N_DENSE * ROW4];      // dense slice of v, 16224 B

    const int tid  = threadIdx.x;
    const int lane = tid & 31;
    const int b    = blockIdx.x * SPB + (tid >> 5);   // one warp per sample

    // Stage dense slice of v (shared by every sample in the grid).
    {
        const float4* v4 = reinterpret_cast<const float4*>(v);
        #pragma unroll
        for (int i = tid; i < N_DENSE * ROW4; i += THREADS)
            s_vd[i] = v4[i];
    }
    __syncthreads();

    const bool valid = (b < B);

    // Per-lane staged scalars (broadcast later via shfl).
    float dxr  = (valid && lane < N_DENSE)
               ? dense_x[b * N_DENSE + lane] : 0.0f;
    int   idxr = (valid && lane < N_SPARSE)
               ? (N_DENSE + lane * ONEHOT + sparse_x[b * N_SPARSE + lane]) : 0;

    float4 acc0 = {0,0,0,0}, acc1 = {0,0,0,0}, acc2 = {0,0,0,0};
    const bool has2 = (lane < ROW4 - 64);       // lane < 14

    // Dense contribution from smem (LDS.128, conflict-free).
    #pragma unroll
    for (int d = 0; d < N_DENSE; ++d) {
        const float xd = __shfl_sync(0xffffffffu, dxr, d);
        const float4* vd = &s_vd[d * ROW4];
        fma4(acc0, xd, vd[lane]);
        fma4(acc1, xd, vd[lane + 32]);
        if (has2) fma4(acc2, xd, vd[lane + 64]);
    }

    // Sparse gathers: 26 random rows, whole warp per row, full-line loads.
    const float4* v4 = reinterpret_cast<const float4*>(v);
    #pragma unroll 2
    for (int i = 0; i < N_SPARSE; ++i) {
        const int r = __shfl_sync(0xffffffffu, idxr, i);
        const float4* row = v4 + (size_t)r * ROW4;
        float4 a = __ldg(row + lane);
        float4 c = __ldg(row + lane + 32);
        add4(acc0, a);
        add4(acc1, c);
        if (has2) {
            float4 e = __ldg(row + lane + 64);
            add4(acc2, e);
        }
    }

    // Per-lane partials: this lane's positions all share k-half (lane&1)*4.
    float4 s4 = {0,0,0,0}, q4 = {0,0,0,0};
    add4(s4, acc0); add4(s4, acc1);
    sqacc4(q4, acc0); sqacc4(q4, acc1);
    if (has2) { add4(s4, acc2); sqacc4(q4, acc2); }

    // Reduce over the 16 lanes sharing this parity (masks keep parity).
    #pragma unroll
    for (int m = 2; m <= 16; m <<= 1) {
        s4.x += __shfl_xor_sync(0xffffffffu, s4.x, m);
        s4.y += __shfl_xor_sync(0xffffffffu, s4.y, m);
        s4.z += __shfl_xor_sync(0xffffffffu, s4.z, m);
        s4.w += __shfl_xor_sync(0xffffffffu, s4.w, m);
        q4.x += __shfl_xor_sync(0xffffffffu, q4.x, m);
        q4.y += __shfl_xor_sync(0xffffffffu, q4.y, m);
        q4.z += __shfl_xor_sync(0xffffffffu, q4.z, m);
        q4.w += __shfl_xor_sync(0xffffffffu, q4.w, m);
    }
    float inter = 0.5f * ((s4.x * s4.x - q4.x) + (s4.y * s4.y - q4.y) +
                          (s4.z * s4.z - q4.z) + (s4.w * s4.w - q4.w));
    // Merge the two k-halves (odd/even parity lanes).
    inter += __shfl_xor_sync(0xffffffffu, inter, 1);

    // Linear part: lane<26 adds W[row_idx], lane<13 adds x_d*W[d].
    float lin = 0.0f;
    if (lane < N_SPARSE) lin = __ldg(W + idxr);
    if (lane < N_DENSE)  lin = fmaf(dxr, __ldg(W + lane), lin);
    #pragma unroll
    for (int m = 16; m >= 1; m >>= 1)
        lin += __shfl_xor_sync(0xffffffffu, lin, m);

    if (lane == 0 && valid) {
        float z = lin + inter + __ldg(bias);
        out[b] = 1.0f / (1.0f + expf(-z));
    }
}

extern "C" void kernel_launch(void* const* d_in, const int* in_sizes, int n_in,
                              void* d_out, int out_size)
{
    const float* dense_x  = (const float*)d_in[0];
    const int*   sparse_x = (const int*)  d_in[1];
    const float* W        = (const float*)d_in[2];
    const float* bias     = (const float*)d_in[3];
    const float* v        = (const float*)d_in[4];
    float*       out      = (float*)d_out;

    const int B = in_sizes[0] / N_DENSE;
    const int grid = (B + SPB - 1) / SPB;
    ffm_kernel<<<grid, THREADS>>>(dense_x, sparse_x, W, bias, v, out, B);
}

// round 10
// speedup vs baseline: 1.8477x; 1.0059x over previous
#include <cuda_runtime.h>

// FFM layer: out[b] = sigmoid( linear(b) + 0.5*sum_k((sum_g f)^2 - sum_g f^2) )
// f[b,g,k] = sum_d dense_x[b,d]*v[d,g,k] + sum_i v[idx[b,i],g,k]
//
// Inputs (metadata order):
//  d_in[0] dense_x  f32 [B,13]
//  d_in[1] sparse_x i32 [B,26]
//  d_in[2] W        f32 [26013]
//  d_in[3] b        f32 [1]
//  d_in[4] v        f32 [26013,39,8]
// Output: f32 [B]
//
// R10: one warp per TWO samples. Row = 312 floats = 78 float4; lane t owns
// float4 positions {t, t+32, t+64 (t<14)}. Gathers for the two samples are
// independent (2x MLP); the dense smem matvec loads each s_vd float4 once
// and feeds both samples (halves LDS traffic vs R9).

namespace {
constexpr int N_DENSE  = 13;
constexpr int N_SPARSE = 26;
constexpr int ONEHOT   = 1000;
constexpr int FIELDS   = 39;
constexpr int ROW4     = FIELDS * 8 / 4;       // 78 float4 per v row
constexpr int WARPS    = 8;
constexpr int SPW      = 2;                    // samples per warp
constexpr int SPB      = WARPS * SPW;          // 16 samples per block
constexpr int THREADS  = WARPS * 32;           // 256
}

__device__ __forceinline__ void fma4(float4& a, float x, const float4& b) {
    a.x = fmaf(x, b.x, a.x); a.y = fmaf(x, b.y, a.y);
    a.z = fmaf(x, b.z, a.z); a.w = fmaf(x, b.w, a.w);
}
__device__ __forceinline__ void add4(float4& a, const float4& b) {
    a.x += b.x; a.y += b.y; a.z += b.z; a.w += b.w;
}
__device__ __forceinline__ void sqacc4(float4& a, const float4& b) {
    a.x = fmaf(b.x, b.x, a.x); a.y = fmaf(b.y, b.y, a.y);
    a.z = fmaf(b.z, b.z, a.z); a.w = fmaf(b.w, b.w, a.w);
}

// Per-sample epilogue: acc0/1/2 -> sigmoid argument contribution (interaction),
// returns value valid in ALL lanes.
__device__ __forceinline__ float reduce_inter(
    float4 acc0, float4 acc1, float4 acc2, bool has2)
{
    float4 s4 = {0,0,0,0}, q4 = {0,0,0,0};
    add4(s4, acc0); add4(s4, acc1);
    sqacc4(q4, acc0); sqacc4(q4, acc1);
    if (has2) { add4(s4, acc2); sqacc4(q4, acc2); }

    // q is linear in k: fold to scalar, reduce over all 32 lanes.
    float q = (q4.x + q4.y) + (q4.z + q4.w);
    #pragma unroll
    for (int m = 16; m >= 1; m >>= 1)
        q += __shfl_xor_sync(0xffffffffu, q, m);

    // s must stay per-k until squared. Lane parity = k-half; xor masks
    // 2..16 preserve parity, so this reduces over the 16 same-parity lanes.
    #pragma unroll
    for (int m = 2; m <= 16; m <<= 1) {
        s4.x += __shfl_xor_sync(0xffffffffu, s4.x, m);
        s4.y += __shfl_xor_sync(0xffffffffu, s4.y, m);
        s4.z += __shfl_xor_sync(0xffffffffu, s4.z, m);
        s4.w += __shfl_xor_sync(0xffffffffu, s4.w, m);
    }
    float ss = (s4.x * s4.x + s4.y * s4.y) + (s4.z * s4.z + s4.w * s4.w);
    ss += __shfl_xor_sync(0xffffffffu, ss, 1);    // merge the two k-halves
    return 0.5f * (ss - q);
}

__device__ __forceinline__ float reduce_lin(float lin)
{
    #pragma unroll
    for (int m = 16; m >= 1; m >>= 1)
        lin += __shfl_xor_sync(0xffffffffu, lin, m);
    return lin;
}

__global__ __launch_bounds__(THREADS) void ffm_kernel(
    const float* __restrict__ dense_x,
    const int*   __restrict__ sparse_x,
    const float* __restrict__ W,
    const float* __restrict__ bias,
    const float* __restrict__ v,
    float*       __restrict__ out,
    int B)
{
    __shared__ float4 s_vd[N_DENSE * ROW4];      // dense slice of v, 16224 B

    const int tid  = threadIdx.x;
    const int lane = tid & 31;
    const int w    = tid >> 5;
    const int bA   = blockIdx.x * SPB + w * SPW;
    const int bB   = bA + 1;

    // Stage dense slice of v (shared by every sample in the grid).
    {
        const float4* v4 = reinterpret_cast<const float4*>(v);
        #pragma unroll
        for (int i = tid; i < N_DENSE * ROW4; i += THREADS)
            s_vd[i] = v4[i];
    }
    __syncthreads();

    const bool vA = (bA < B), vB = (bB < B);

    // Per-lane staged scalars (broadcast later via shfl).
    float dxA = (vA && lane < N_DENSE) ? dense_x[bA * N_DENSE + lane] : 0.0f;
    float dxB = (vB && lane < N_DENSE) ? dense_x[bB * N_DENSE + lane] : 0.0f;
    int   idxA = (vA && lane < N_SPARSE)
               ? (N_DENSE + lane * ONEHOT + sparse_x[bA * N_SPARSE + lane]) : 0;
    int   idxB = (vB && lane < N_SPARSE)
               ? (N_DENSE + lane * ONEHOT + sparse_x[bB * N_SPARSE + lane]) : 0;

    float4 a0 = {0,0,0,0}, a1 = {0,0,0,0}, a2 = {0,0,0,0};
    float4 c0 = {0,0,0,0}, c1 = {0,0,0,0}, c2 = {0,0,0,0};
    const bool has2 = (lane < ROW4 - 64);        // lane < 14

    // Dense matvec: each s_vd float4 is loaded ONCE and feeds both samples.
    #pragma unroll
    for (int d = 0; d < N_DENSE; ++d) {
        const float xA = __shfl_sync(0xffffffffu, dxA, d);
        const float xB = __shfl_sync(0xffffffffu, dxB, d);
        const float4* vd = &s_vd[d * ROW4];
        float4 t0 = vd[lane];
        float4 t1 = vd[lane + 32];
        fma4(a0, xA, t0); fma4(c0, xB, t0);
        fma4(a1, xA, t1); fma4(c1, xB, t1);
        if (has2) {
            float4 t2 = vd[lane + 64];
            fma4(a2, xA, t2); fma4(c2, xB, t2);
        }
    }

    // Sparse gathers: 26 rows per sample, two independent chains per warp.
    const float4* v4 = reinterpret_cast<const float4*>(v);
    #pragma unroll
    for (int i = 0; i < N_SPARSE; ++i) {
        const int rA = __shfl_sync(0xffffffffu, idxA, i);
        const int rB = __shfl_sync(0xffffffffu, idxB, i);
        const float4* ra = v4 + (size_t)rA * ROW4;
        const float4* rb = v4 + (size_t)rB * ROW4;
        float4 tA0 = __ldg(ra + lane);
        float4 tB0 = __ldg(rb + lane);
        float4 tA1 = __ldg(ra + lane + 32);
        float4 tB1 = __ldg(rb + lane + 32);
        add4(a0, tA0); add4(c0, tB0);
        add4(a1, tA1); add4(c1, tB1);
        if (has2) {
            float4 tA2 = __ldg(ra + lane + 64);
            float4 tB2 = __ldg(rb + lane + 64);
            add4(a2, tA2); add4(c2, tB2);
        }
    }

    // Interaction terms.
    float interA = reduce_inter(a0, a1, a2, has2);
    float interB = reduce_inter(c0, c1, c2, has2);

    // Linear terms.
    float linA = 0.0f, linB = 0.0f;
    if (lane < N_SPARSE) { linA = __ldg(W + idxA); linB = __ldg(W + idxB); }
    if (lane < N_DENSE) {
        const float wd = __ldg(W + lane);
        linA = fmaf(dxA, wd, linA);
        linB = fmaf(dxB, wd, linB);
    }
    linA = reduce_lin(linA);
    linB = reduce_lin(linB);

    if (lane == 0) {
        const float bs = __ldg(bias);
        if (vA) {
            float z = linA + interA + bs;
            out[bA] = 1.0f / (1.0f + expf(-z));
        }
        if (vB) {
            float z = linB + interB + bs;
            out[bB] = 1.0f / (1.0f + expf(-z));
        }
    }
}

extern "C" void kernel_launch(void* const* d_in, const int* in_sizes, int n_in,
                              void* d_out, int out_size)
{
    const float* dense_x  = (const float*)d_in[0];
    const int*   sparse_x = (const int*)  d_in[1];
    const float* W        = (const float*)d_in[2];
    const float* bias     = (const float*)d_in[3];
    const float* v        = (const float*)d_in[4];
    float*       out      = (float*)d_out;

    const int B = in_sizes[0] / N_DENSE;
    const int grid = (B + SPB - 1) / SPB;
    ffm_kernel<<<grid, THREADS>>>(dense_x, sparse_x, W, bias, v, out, B);
}

// round 11
// speedup vs baseline: 1.8683x; 1.0112x over previous
#include <cuda_runtime.h>
#include <cuda_fp16.h>

// FFM layer: out[b] = sigmoid( linear(b) + 0.5*sum_k((sum_g f)^2 - sum_g f^2) )
// f[b,g,k] = sum_d dense_x[b,d]*v[d,g,k] + sum_i v[idx[b,i],g,k]
//
// Inputs: d_in[0] dense_x f32[B,13], d_in[1] sparse_x i32[B,26],
//         d_in[2] W f32[26013], d_in[3] b f32[1], d_in[4] v f32[26013,39,8]
// Output: f32 [B]
//
// R11: the kernel is at the LTS chip cap (~6300 B/cyc) — 531 MB of fp32
// gather traffic IS the runtime. Halve it: pre-kernel converts v to an fp16
// __device__ scratch; main kernel gathers fp16 (266 MB). fp16 row = 39 uint4,
// one uint4 per field (8 k-values) -> lane t owns fields {t, 32+t(t<7)}.
// Sparse adds in two alternating half2 chains (HADD2), merged to fp32 once.
// Dense part stays fp32 via xor-swizzled smem (conflict-free LDS.128).

namespace {
constexpr int N_DENSE  = 13;
constexpr int N_SPARSE = 26;
constexpr int ONEHOT   = 1000;
constexpr int FIELDS   = 39;
constexpr int ROWF     = FIELDS * 8;           // 312 floats per v row
constexpr int ROWH4    = FIELDS;               // 39 uint4 per fp16 row
constexpr int ROW4     = ROWF / 4;             // 78 float4 per fp32 row
constexpr int N_ROWS   = N_DENSE + N_SPARSE * ONEHOT;  // 26013
constexpr int TOT      = N_ROWS * ROWF;        // 8,116,056 halves
constexpr int SPB      = 8;                    // one warp per sample
constexpr int THREADS  = 256;
}

__device__ __align__(16) __half g_vh[TOT];     // 16.2 MB fp16 table

// ---------------------------------------------------------------- convert --
__global__ void __launch_bounds__(256) cvt_kernel(const float4* __restrict__ v4)
{
    const int n = TOT / 8;                     // 1,014,507 uint4 outputs
    int i = blockIdx.x * blockDim.x + threadIdx.x;
    if (i >= n) return;
    float4 a = __ldg(v4 + 2 * i);
    float4 b = __ldg(v4 + 2 * i + 1);
    __half2 h0 = __floats2half2_rn(a.x, a.y);
    __half2 h1 = __floats2half2_rn(a.z, a.w);
    __half2 h2 = __floats2half2_rn(b.x, b.y);
    __half2 h3 = __floats2half2_rn(b.z, b.w);
    uint4 o;
    o.x = *reinterpret_cast<unsigned*>(&h0);
    o.y = *reinterpret_cast<unsigned*>(&h1);
    o.z = *reinterpret_cast<unsigned*>(&h2);
    o.w = *reinterpret_cast<unsigned*>(&h3);
    reinterpret_cast<uint4*>(g_vh)[i] = o;
}

// ------------------------------------------------------------------- main --
__device__ __forceinline__ __half2 u2h2(unsigned u) {
    __half2 h; *reinterpret_cast<unsigned*>(&h) = u; return h;
}

__global__ __launch_bounds__(THREADS) void ffm_kernel(
    const float* __restrict__ dense_x,
    const int*   __restrict__ sparse_x,
    const float* __restrict__ W,
    const float* __restrict__ bias,
    const float* __restrict__ v,
    float*       __restrict__ out,
    int B)
{
    // fp32 dense slice of v, xor-swizzled so per-field float4 pairs
    // (stride 32B across lanes) are bank-conflict-free.
    __shared__ float4 s_vd[N_DENSE * ROW4];

    const int tid  = threadIdx.x;
    const int lane = tid & 31;
    const int b    = blockIdx.x * SPB + (tid >> 5);

    {
        const float4* v4 = reinterpret_cast<const float4*>(v);
        #pragma unroll
        for (int j = tid; j < N_DENSE * ROW4; j += THREADS) {
            int d = j / ROW4, s = j % ROW4;
            int phys = s ^ ((s >> 3) & 1);
            s_vd[d * ROW4 + phys] = __ldg(v4 + d * ROW4 + s);
        }
    }
    __syncthreads();

    const bool valid = (b < B);
    const bool hasB  = (lane < FIELDS - 32);   // lane < 7 owns field 32+lane

    float dxr  = (valid && lane < N_DENSE) ? dense_x[b * N_DENSE + lane] : 0.0f;
    int   idxr = (valid && lane < N_SPARSE)
               ? (N_DENSE + lane * ONEHOT + sparse_x[b * N_SPARSE + lane])
               : N_DENSE;

    // Physical smem slots for this lane's fields (A = lane, B = 32+lane).
    const int jA0 = 2 * lane,      jA1 = 2 * lane + 1;
    const int jB0 = 64 + 2 * lane, jB1 = 65 + 2 * lane;
    const int pA0 = jA0 ^ ((jA0 >> 3) & 1), pA1 = jA1 ^ ((jA1 >> 3) & 1);
    const int pB0 = jB0 ^ ((jB0 >> 3) & 1), pB1 = jB1 ^ ((jB1 >> 3) & 1);

    float fA[8], fB[8];
    #pragma unroll
    for (int k = 0; k < 8; ++k) { fA[k] = 0.0f; fB[k] = 0.0f; }

    // ---- dense matvec (fp32, smem) ----
    #pragma unroll
    for (int d = 0; d < N_DENSE; ++d) {
        const float xd = __shfl_sync(0xffffffffu, dxr, d);
        const float4* row = &s_vd[d * ROW4];
        float4 t0 = row[pA0], t1 = row[pA1];
        fA[0] = fmaf(xd, t0.x, fA[0]); fA[1] = fmaf(xd, t0.y, fA[1]);
        fA[2] = fmaf(xd, t0.z, fA[2]); fA[3] = fmaf(xd, t0.w, fA[3]);
        fA[4] = fmaf(xd, t1.x, fA[4]); fA[5] = fmaf(xd, t1.y, fA[5]);
        fA[6] = fmaf(xd, t1.z, fA[6]); fA[7] = fmaf(xd, t1.w, fA[7]);
        if (hasB) {
            float4 t2 = row[pB0], t3 = row[pB1];
            fB[0] = fmaf(xd, t2.x, fB[0]); fB[1] = fmaf(xd, t2.y, fB[1]);
            fB[2] = fmaf(xd, t2.z, fB[2]); fB[3] = fmaf(xd, t2.w, fB[3]);
            fB[4] = fmaf(xd, t3.x, fB[4]); fB[5] = fmaf(xd, t3.y, fB[5]);
            fB[6] = fmaf(xd, t3.z, fB[6]); fB[7] = fmaf(xd, t3.w, fB[7]);
        }
    }

    // ---- sparse gathers (fp16, two alternating half2 chains) ----
    __half2 cA[2][4], cB[2][4];
    #pragma unroll
    for (int c = 0; c < 2; ++c)
        #pragma unroll
        for (int m = 0; m < 4; ++m) {
            cA[c][m] = __floats2half2_rn(0.0f, 0.0f);
            cB[c][m] = __floats2half2_rn(0.0f, 0.0f);
        }

    const uint4* vh4 = reinterpret_cast<const uint4*>(g_vh);
    #pragma unroll
    for (int i = 0; i < N_SPARSE; ++i) {
        const int r = __shfl_sync(0xffffffffu, idxr, i);
        const uint4* rp = vh4 + (size_t)r * ROWH4;
        const int c = i & 1;
        uint4 hA = __ldg(rp + lane);
        cA[c][0] = __hadd2(cA[c][0], u2h2(hA.x));
        cA[c][1] = __hadd2(cA[c][1], u2h2(hA.y));
        cA[c][2] = __hadd2(cA[c][2], u2h2(hA.z));
        cA[c][3] = __hadd2(cA[c][3], u2h2(hA.w));
        if (hasB) {
            uint4 hB = __ldg(rp + 32 + lane);
            cB[c][0] = __hadd2(cB[c][0], u2h2(hB.x));
            cB[c][1] = __hadd2(cB[c][1], u2h2(hB.y));
            cB[c][2] = __hadd2(cB[c][2], u2h2(hB.z));
            cB[c][3] = __hadd2(cB[c][3], u2h2(hB.w));
        }
    }
    // Merge chains into fp32 accumulators (fB stays 0 for lanes >= 7).
    #pragma unroll
    for (int m = 0; m < 4; ++m) {
        float2 a0 = __half22float2(cA[0][m]);
        float2 a1 = __half22float2(cA[1][m]);
        fA[2 * m]     += a0.x + a1.x;
        fA[2 * m + 1] += a0.y + a1.y;
        float2 b0 = __half22float2(cB[0][m]);
        float2 b1 = __half22float2(cB[1][m]);
        fB[2 * m]     += b0.x + b1.x;
        fB[2 * m + 1] += b0.y + b1.y;
    }

    // ---- epilogue ----
    float s[8], q = 0.0f;
    #pragma unroll
    for (int k = 0; k < 8; ++k) {
        s[k] = fA[k] + fB[k];
        q = fmaf(fA[k], fA[k], q);
        q = fmaf(fB[k], fB[k], q);
    }

    float lin = 0.0f;
    if (lane < N_SPARSE) lin = __ldg(W + idxr);
    if (lane < N_DENSE)  lin = fmaf(dxr, __ldg(W + lane), lin);

    #pragma unroll
    for (int m = 16; m >= 1; m >>= 1) {
        q   += __shfl_xor_sync(0xffffffffu, q, m);
        lin += __shfl_xor_sync(0xffffffffu, lin, m);
    }
    #pragma unroll
    for (int k = 0; k < 8; ++k)
        #pragma unroll
        for (int m = 16; m >= 1; m >>= 1)
            s[k] += __shfl_xor_sync(0xffffffffu, s[k], m);

    float ss = 0.0f;
    #pragma unroll
    for (int k = 0; k < 8; ++k) ss = fmaf(s[k], s[k], ss);

    if (lane == 0 && valid) {
        float z = lin + 0.5f * (ss - q) + __ldg(bias);
        out[b] = 1.0f / (1.0f + expf(-z));
    }
}

extern "C" void kernel_launch(void* const* d_in, const int* in_sizes, int n_in,
                              void* d_out, int out_size)
{
    const float* dense_x  = (const float*)d_in[0];
    const int*   sparse_x = (const int*)  d_in[1];
    const float* W        = (const float*)d_in[2];
    const float* bias     = (const float*)d_in[3];
    const float* v        = (const float*)d_in[4];
    float*       out      = (float*)d_out;

    const int B = in_sizes[0] / N_DENSE;

    const int ncvt = TOT / 8;
    cvt_kernel<<<(ncvt + 255) / 256, 256>>>(
        reinterpret_cast<const float4*>(v));

    const int grid = (B + SPB - 1) / SPB;
    ffm_kernel<<<grid, THREADS>>>(dense_x, sparse_x, W, bias, v, out, B);
}